// round 16
// baseline (speedup 1.0000x reference)
#include <cuda_runtime.h>
#include <cuda_fp16.h>

#define BB   16
#define NN   1024
#define DIMC 512
#define HH   8

__device__ __half g_QKV[(size_t)BB * NN * 1536];
__device__ __half g_S[(size_t)BB * HH * NN * NN];   // unnormalized exp
__device__ __half g_O[(size_t)BB * NN * 512];
__device__ float  g_Lp[(size_t)BB * HH * NN * 8];   // partial row sums
__device__ __half g_x16[(size_t)BB * NN * DIMC];
__device__ __half g_Wq16[DIMC * 512];
__device__ __half g_Wkv16[DIMC * 1024];
__device__ __half g_Wout16[512 * DIMC];

__device__ __forceinline__ unsigned smem_u32(const void* p) {
    return (unsigned)__cvta_generic_to_shared(p);
}
#define LDM_X4(R0,R1,R2,R3,ADDR) \
    asm volatile("ldmatrix.sync.aligned.m8n8.x4.shared.b16 {%0,%1,%2,%3}, [%4];" \
        : "=r"(R0),"=r"(R1),"=r"(R2),"=r"(R3) : "r"(ADDR))
#define LDM_X2(R0,R1,ADDR) \
    asm volatile("ldmatrix.sync.aligned.m8n8.x2.shared.b16 {%0,%1}, [%2];" \
        : "=r"(R0),"=r"(R1) : "r"(ADDR))
#define LDM_X2_T(R0,R1,ADDR) \
    asm volatile("ldmatrix.sync.aligned.m8n8.x2.trans.shared.b16 {%0,%1}, [%2];" \
        : "=r"(R0),"=r"(R1) : "r"(ADDR))
#define MMA16816(C,A,B) \
    asm volatile("mma.sync.aligned.m16n8k16.row.col.f32.f16.f16.f32 " \
        "{%0,%1,%2,%3}, {%4,%5,%6,%7}, {%8,%9}, {%0,%1,%2,%3};" \
        : "+f"((C)[0]),"+f"((C)[1]),"+f"((C)[2]),"+f"((C)[3]) \
        : "r"((A)[0]),"r"((A)[1]),"r"((A)[2]),"r"((A)[3]),"r"((B)[0]),"r"((B)[1]))

__global__ void f2h_k(const float* __restrict__ in, __half* __restrict__ out, int n)
{
    int i = (blockIdx.x * blockDim.x + threadIdx.x) * 4;
    if (i < n) {
        float4 f = *(const float4*)&in[i];
        __half2 a = __float22half2_rn(make_float2(f.x, f.y));
        __half2 b = __float22half2_rn(make_float2(f.z, f.w));
        *(uint2*)&out[i] = make_uint2(*(unsigned*)&a, *(unsigned*)&b);
    }
}

// ---------------- hgemm_nn (projections), unchanged ----------------
template <typename TC>
__global__ void __launch_bounds__(256) hgemm_nn(
    const __half* __restrict__ A, int lda,
    const __half* __restrict__ B, int ldb,
    TC* __restrict__ C, int ldc,
    int Kc, const float* __restrict__ bias)
{
    __shared__ __half As[2][128][40];
    __shared__ __half Bs[2][32][136];
    const int t = threadIdx.x, bm = blockIdx.y * 128, bn = blockIdx.x * 128;
    const int wid = t >> 5, lane = t & 31;
    const int wm = (wid >> 1) * 32, wn = (wid & 1) * 64;

    uint4 aSt[2], bSt[2];
    auto loadAB = [&](int k0) {
        #pragma unroll
        for (int r = 0; r < 2; r++) {
            int idx = r * 256 + t, row = idx >> 2, c8 = idx & 3;
            aSt[r] = *(const uint4*)&A[(size_t)(bm + row) * lda + k0 + c8 * 8];
        }
        #pragma unroll
        for (int r = 0; r < 2; r++) {
            int idx = r * 256 + t, row = idx >> 4, c8 = idx & 15;
            bSt[r] = *(const uint4*)&B[(size_t)(k0 + row) * ldb + bn + c8 * 8];
        }
    };
    auto storeAB = [&](int buf) {
        #pragma unroll
        for (int r = 0; r < 2; r++) {
            int idx = r * 256 + t, row = idx >> 2, c8 = idx & 3;
            *(uint4*)&As[buf][row][c8 * 8] = aSt[r];
        }
        #pragma unroll
        for (int r = 0; r < 2; r++) {
            int idx = r * 256 + t, row = idx >> 4, c8 = idx & 15;
            *(uint4*)&Bs[buf][row][c8 * 8] = bSt[r];
        }
    };

    float acc[2][8][4];
    #pragma unroll
    for (int mf = 0; mf < 2; mf++)
        #pragma unroll
        for (int nf = 0; nf < 8; nf++)
            #pragma unroll
            for (int e = 0; e < 4; e++) acc[mf][nf][e] = 0.f;

    loadAB(0); storeAB(0);
    __syncthreads();
    int buf = 0;
    for (int k0 = 0; k0 < Kc; k0 += 32) {
        const bool more = (k0 + 32) < Kc;
        if (more) loadAB(k0 + 32);
        #pragma unroll
        for (int kk = 0; kk < 32; kk += 16) {
            unsigned a[2][4];
            #pragma unroll
            for (int mf = 0; mf < 2; mf++)
                LDM_X4(a[mf][0], a[mf][1], a[mf][2], a[mf][3],
                       smem_u32(&As[buf][wm + mf * 16 + (lane & 15)][kk + 8 * (lane >> 4)]));
            #pragma unroll
            for (int nf = 0; nf < 8; nf++) {
                unsigned bf[2];
                LDM_X2_T(bf[0], bf[1],
                    smem_u32(&Bs[buf][kk + (lane & 7) + 8 * ((lane >> 3) & 1)][wn + nf * 8]));
                #pragma unroll
                for (int mf = 0; mf < 2; mf++)
                    MMA16816(acc[mf][nf], a[mf], bf);
            }
        }
        if (more) { storeAB(buf ^ 1); __syncthreads(); buf ^= 1; }
    }

    #pragma unroll
    for (int mf = 0; mf < 2; mf++)
        #pragma unroll
        for (int nf = 0; nf < 8; nf++) {
            int m = bm + wm + mf * 16 + (lane >> 2);
            int n = bn + wn + nf * 8 + (lane & 3) * 2;
            float c0 = acc[mf][nf][0], c1 = acc[mf][nf][1];
            float c2 = acc[mf][nf][2], c3 = acc[mf][nf][3];
            if (bias) {
                float b0 = bias[n], b1 = bias[n + 1];
                c0 += b0; c1 += b1; c2 += b0; c3 += b1;
            }
            if constexpr (sizeof(TC) == 2) {
                *(__half2*)&C[(size_t)m * ldc + n] = __float22half2_rn(make_float2(c0, c1));
                *(__half2*)&C[(size_t)(m + 8) * ldc + n] = __float22half2_rn(make_float2(c2, c3));
            } else {
                *(float2*)&C[(size_t)m * ldc + n]       = make_float2(c0, c1);
                *(float2*)&C[(size_t)(m + 8) * ldc + n] = make_float2(c2, c3);
            }
        }
}

// ---------------------------------------------------------------------------
// K1: QK^T (all 8 heads) + premix(+scale fold) + diag + exp. Writes
// unnormalized exp to S, partial row sums to Lp. Block=(jblk,iblk,b), 256 thr.
// ---------------------------------------------------------------------------
#define K1_SMEM (2*64*72*2 + 2*128*72*2 + 8*64*136*2 + 64*4)   // 194816

__global__ void __launch_bounds__(256) qkmixexp_k(
    const __half* __restrict__ QKV, __half* __restrict__ S,
    float* __restrict__ Lp,
    const float* __restrict__ scale, const float* __restrict__ mpre)
{
    extern __shared__ char smraw[];
    __half*  Qs  = (__half*)smraw;                  // [2][64][72]
    __half*  Ks  = Qs + 2 * 64 * 72;                // [2][128][72]
    __half*  ds  = Ks + 2 * 128 * 72;               // [8][64][136]
    __half2* wsm = (__half2*)(ds + 8 * 64 * 136);   // [64]

    const int b = blockIdx.z, i0 = blockIdx.y * 64, j0 = blockIdx.x * 128;
    const int t = threadIdx.x, w = t >> 5, lane = t & 31;
    const int wm = (w >> 1) * 16, wn = (w & 1) * 64;

    if (t < 64) wsm[t] = __float2half2_rn(mpre[t] * scale[t >> 3]);

    const __half* Qg = QKV + (size_t)b * NN * 1536 + (size_t)i0 * 1536;
    const __half* Kg = QKV + (size_t)b * NN * 1536 + 512 + (size_t)j0 * 1536;

    uint4 qst[2], kst[4];
    auto loadQK = [&](int h) {
        #pragma unroll
        for (int r = 0; r < 2; r++) {
            int idx = r * 256 + t, row = idx >> 3, c = idx & 7;
            qst[r] = *(const uint4*)&Qg[(size_t)row * 1536 + h * 64 + c * 8];
        }
        #pragma unroll
        for (int r = 0; r < 4; r++) {
            int idx = r * 256 + t, row = idx >> 3, c = idx & 7;
            kst[r] = *(const uint4*)&Kg[(size_t)row * 1536 + h * 64 + c * 8];
        }
    };
    auto storeQK = [&](int buf) {
        __half* Qb = Qs + buf * 64 * 72;
        __half* Kb = Ks + buf * 128 * 72;
        #pragma unroll
        for (int r = 0; r < 2; r++) {
            int idx = r * 256 + t, row = idx >> 3, c = idx & 7;
            *(uint4*)&Qb[row * 72 + c * 8] = qst[r];
        }
        #pragma unroll
        for (int r = 0; r < 4; r++) {
            int idx = r * 256 + t, row = idx >> 3, c = idx & 7;
            *(uint4*)&Kb[row * 72 + c * 8] = kst[r];
        }
    };

    loadQK(0); storeQK(0);
    __syncthreads();

    for (int h = 0; h < 8; h++) {
        if (h < 7) loadQK(h + 1);
        const __half* Qb = Qs + (h & 1) * 64 * 72;
        const __half* Kb = Ks + (h & 1) * 128 * 72;

        float acc[8][4];
        #pragma unroll
        for (int nf = 0; nf < 8; nf++)
            #pragma unroll
            for (int e = 0; e < 4; e++) acc[nf][e] = 0.f;

        #pragma unroll
        for (int kf = 0; kf < 4; kf++) {
            unsigned a[4];
            LDM_X4(a[0], a[1], a[2], a[3],
                   smem_u32(&Qb[(wm + (lane & 15)) * 72 + kf * 16 + 8 * (lane >> 4)]));
            #pragma unroll
            for (int nf = 0; nf < 8; nf++) {
                unsigned bf[2];
                LDM_X2(bf[0], bf[1],
                       smem_u32(&Kb[(wn + nf * 8 + (lane & 7)) * 72 + kf * 16 + 8 * ((lane >> 3) & 1)]));
                MMA16816(acc[nf], a, bf);
            }
        }

        __half* dh = ds + h * 64 * 136;
        #pragma unroll
        for (int nf = 0; nf < 8; nf++) {
            int rr = wm + (lane >> 2), cc = wn + nf * 8 + (lane & 3) * 2;
            *(__half2*)&dh[rr * 136 + cc] = __float22half2_rn(make_float2(acc[nf][0], acc[nf][1]));
            *(__half2*)&dh[(rr + 8) * 136 + cc] = __float22half2_rn(make_float2(acc[nf][2], acc[nf][3]));
        }
        if (h < 7) storeQK((h + 1) & 1);
        __syncthreads();
    }

    // premix + diag + exp + store + partial sums
    __half2 wreg[8][8];
    #pragma unroll
    for (int h = 0; h < 8; h++)
        #pragma unroll
        for (int g = 0; g < 8; g++) wreg[h][g] = wsm[h * 8 + g];

    const int row = t >> 2, q = t & 3;
    const int dj = i0 + row - j0;
    float rsum[8];
    #pragma unroll
    for (int g = 0; g < 8; g++) rsum[g] = 0.f;

    #pragma unroll
    for (int c4 = 0; c4 < 4; c4++) {
        int colh = q * 32 + c4 * 8;
        uint4 ev[8];
        #pragma unroll
        for (int h = 0; h < 8; h++)
            ev[h] = *(const uint4*)&ds[h * 64 * 136 + row * 136 + colh];

        #pragma unroll
        for (int g = 0; g < 8; g++) {
            __half2 lg[4];
            #pragma unroll
            for (int e = 0; e < 4; e++) lg[e] = __float2half2_rn(0.f);
            #pragma unroll
            for (int h = 0; h < 8; h++) {
                const __half2* vp = (const __half2*)&ev[h];
                #pragma unroll
                for (int e = 0; e < 4; e++)
                    lg[e] = __hfma2(wreg[h][g], vp[e], lg[e]);
            }
            if (dj >= colh && dj < colh + 8) {
                int d = dj - colh, p = d >> 1;
                const __half z = __float2half(0.f);
                lg[p] = (d & 1) ? __halves2half2(__low2half(lg[p]), z)
                                : __halves2half2(z, __high2half(lg[p]));
            }
            __half2 eo[4];
            float rs = 0.f;
            #pragma unroll
            for (int e = 0; e < 4; e++) {
                float2 f = __half22float2(lg[e]);
                f.x = __expf(f.x); f.y = __expf(f.y);
                rs += f.x + f.y;
                eo[e] = __float22half2_rn(f);
            }
            rsum[g] += rs;
            *(uint4*)&S[(((size_t)b * 8 + g) * NN + i0 + row) * NN + j0 + colh] = *(uint4*)eo;
        }
    }
    #pragma unroll
    for (int g = 0; g < 8; g++) {
        float rv = rsum[g];
        rv += __shfl_xor_sync(0xffffffffu, rv, 1);
        rv += __shfl_xor_sync(0xffffffffu, rv, 2);
        if (q == 0)
            Lp[(((size_t)b * 8 + g) * NN + i0 + row) * 8 + blockIdx.x] = rv;
    }
}

// ---------------------------------------------------------------------------
// K2: postmix (1/l folded, fp32) + AV for all 8 heads. Block=(32i, b), 512 thr.
// ---------------------------------------------------------------------------
#define K2_SMEM (8*32*72*2 + 8*32*72*2 + 64*520*2 + 32*8*4 + 32*64*4)  // 149504

__global__ void __launch_bounds__(512) mixav_k(
    const __half* __restrict__ S, const __half* __restrict__ QKV,
    const float* __restrict__ Lp, __half* __restrict__ O,
    const float* __restrict__ mpost)
{
    extern __shared__ char smraw[];
    __half* Es = (__half*)smraw;            // [8][32][72]
    __half* P  = Es + 8 * 32 * 72;          // [8][32][72]
    __half* Vs = P + 8 * 32 * 72;           // [64][520]
    float*  rl  = (float*)(Vs + 64 * 520);  // [32][8]
    float*  wps = rl + 32 * 8;              // [32][64]

    const int b = blockIdx.y, i0 = blockIdx.x * 32;
    const int t = threadIdx.x, w = t >> 5, lane = t & 31;

    if (t < 256) {
        int i = t >> 3, h = t & 7;
        const float* p = &Lp[(((size_t)b * 8 + h) * NN + i0 + i) * 8];
        float s = p[0] + p[1] + p[2] + p[3] + p[4] + p[5] + p[6] + p[7];
        rl[i * 8 + h] = __frcp_rn(s);
    }
    __syncthreads();
    #pragma unroll
    for (int r = 0; r < 4; r++) {
        int idx = r * 512 + t, i = idx >> 6, k = idx & 63;
        wps[i * 64 + k] = mpost[k] * rl[i * 8 + (k >> 3)];
    }

    const int g = w >> 1, mb = (w & 1) * 16;
    float acc[8][4];
    #pragma unroll
    for (int nf = 0; nf < 8; nf++)
        #pragma unroll
        for (int e = 0; e < 4; e++) acc[nf][e] = 0.f;

    const __half* Vg = QKV + (size_t)b * NN * 1536 + 1024;

    for (int jc = 0; jc < NN; jc += 64) {
        __syncthreads();
        #pragma unroll
        for (int r = 0; r < 4; r++) {
            int idx = r * 512 + t, h = idx >> 8, row = (idx >> 3) & 31, c = idx & 7;
            *(uint4*)&Es[h * 2304 + row * 72 + c * 8] =
                *(const uint4*)&S[(((size_t)b * 8 + h) * NN + i0 + row) * NN + jc + c * 8];
        }
        #pragma unroll
        for (int r = 0; r < 8; r++) {
            int idx = r * 512 + t, row = idx >> 6, c = idx & 63;
            *(uint4*)&Vs[row * 520 + c * 8] =
                *(const uint4*)&Vg[(size_t)(jc + row) * 1536 + c * 8];
        }
        __syncthreads();

        {   // postmix -> P (fp32 accum)
            int i = t >> 4, j4 = (t & 15) * 4;
            float f[8][4];
            #pragma unroll
            for (int gg = 0; gg < 8; gg++)
                #pragma unroll
                for (int e = 0; e < 4; e++) f[gg][e] = 0.f;
            #pragma unroll
            for (int h = 0; h < 8; h++) {
                __half2 ea = *(__half2*)&Es[h * 2304 + i * 72 + j4];
                __half2 eb = *(__half2*)&Es[h * 2304 + i * 72 + j4 + 2];
                float2 fa = __half22float2(ea), fb = __half22float2(eb);
                #pragma unroll
                for (int gg = 0; gg < 8; gg++) {
                    float wv = wps[i * 64 + h * 8 + gg];
                    f[gg][0] += wv * fa.x; f[gg][1] += wv * fa.y;
                    f[gg][2] += wv * fb.x; f[gg][3] += wv * fb.y;
                }
            }
            #pragma unroll
            for (int gg = 0; gg < 8; gg++) {
                *(__half2*)&P[gg * 2304 + i * 72 + j4] =
                    __float22half2_rn(make_float2(f[gg][0], f[gg][1]));
                *(__half2*)&P[gg * 2304 + i * 72 + j4 + 2] =
                    __float22half2_rn(make_float2(f[gg][2], f[gg][3]));
            }
        }
        __syncthreads();

        #pragma unroll
        for (int kk = 0; kk < 64; kk += 16) {
            unsigned a[4];
            LDM_X4(a[0], a[1], a[2], a[3],
                   smem_u32(&P[g * 2304 + (mb + (lane & 15)) * 72 + kk + 8 * (lane >> 4)]));
            #pragma unroll
            for (int nf = 0; nf < 8; nf++) {
                unsigned bf[2];
                LDM_X2_T(bf[0], bf[1],
                    smem_u32(&Vs[(kk + (lane & 7) + 8 * ((lane >> 3) & 1)) * 520 + g * 64 + nf * 8]));
                MMA16816(acc[nf], a, bf);
            }
        }
    }

    #pragma unroll
    for (int nf = 0; nf < 8; nf++) {
        int row = i0 + mb + (lane >> 2);
        int col = g * 64 + nf * 8 + (lane & 3) * 2;
        *(__half2*)&O[((size_t)b * NN + row) * 512 + col] =
            __float22half2_rn(make_float2(acc[nf][0], acc[nf][1]));
        *(__half2*)&O[((size_t)b * NN + row + 8) * 512 + col] =
            __float22half2_rn(make_float2(acc[nf][2], acc[nf][3]));
    }
}

// ---------------------------------------------------------------------------
extern "C" void kernel_launch(void* const* d_in, const int* in_sizes, int n_in,
                              void* d_out, int out_size)
{
    const float* x     = (const float*)d_in[0];
    const float* Wq    = (const float*)d_in[1];
    const float* Wkv   = (const float*)d_in[2];
    const float* scale = (const float*)d_in[3];
    const float* mpre  = (const float*)d_in[4];
    const float* mpost = (const float*)d_in[5];
    const float* Wout  = (const float*)d_in[6];
    const float* bout  = (const float*)d_in[7];
    float* out = (float*)d_out;

    __half *qkv, *S, *O, *x16, *wq16, *wkv16, *wout16;
    float* Lp;
    cudaGetSymbolAddress((void**)&qkv,    g_QKV);
    cudaGetSymbolAddress((void**)&S,      g_S);
    cudaGetSymbolAddress((void**)&O,      g_O);
    cudaGetSymbolAddress((void**)&Lp,     g_Lp);
    cudaGetSymbolAddress((void**)&x16,    g_x16);
    cudaGetSymbolAddress((void**)&wq16,   g_Wq16);
    cudaGetSymbolAddress((void**)&wkv16,  g_Wkv16);
    cudaGetSymbolAddress((void**)&wout16, g_Wout16);

    cudaFuncSetAttribute(qkmixexp_k, cudaFuncAttributeMaxDynamicSharedMemorySize, K1_SMEM);
    cudaFuncSetAttribute(mixav_k,    cudaFuncAttributeMaxDynamicSharedMemorySize, K2_SMEM);

    {
        int nx = BB * NN * DIMC;
        f2h_k<<<nx / 4 / 256, 256>>>(x, x16, nx);
        f2h_k<<<DIMC * 512  / 4 / 256, 256>>>(Wq,   wq16,   DIMC * 512);
        f2h_k<<<DIMC * 1024 / 4 / 256, 256>>>(Wkv,  wkv16,  DIMC * 1024);
        f2h_k<<<512 * DIMC  / 4 / 256, 256>>>(Wout, wout16, 512 * DIMC);
    }

    hgemm_nn<__half><<<dim3(4, 128), 256>>>(x16, DIMC, wq16, 512, qkv, 1536, DIMC, nullptr);
    hgemm_nn<__half><<<dim3(8, 128), 256>>>(x16, DIMC, wkv16, 1024, qkv + 512, 1536, DIMC, nullptr);

    qkmixexp_k<<<dim3(8, 16, BB), 256, K1_SMEM>>>(qkv, S, Lp, scale, mpre);
    mixav_k<<<dim3(NN / 32, BB), 512, K2_SMEM>>>(S, qkv, Lp, O, mpost);

    hgemm_nn<float><<<dim3(4, 128), 256>>>(O, 512, wout16, DIMC, out, DIMC, DIMC, bout);
}